// round 2
// baseline (speedup 1.0000x reference)
#include <cuda_runtime.h>
#include <cuda_bf16.h>

#define NN   2048
#define RR   4
#define NT   512        // threads per CTA (must be 512: one radix-4 quad per thread)

// Precomputed spectra (in the DIF-permuted domain), filled each launch.
__device__ float2 g_Ghat[RR][NN];
__device__ float2 g_Hhat[RR][NN];

__device__ __forceinline__ float2 cadd(float2 a, float2 b){ return make_float2(a.x+b.x, a.y+b.y); }
__device__ __forceinline__ float2 csub(float2 a, float2 b){ return make_float2(a.x-b.x, a.y-b.y); }
__device__ __forceinline__ float2 cmul(float2 a, float2 b){
    return make_float2(a.x*b.x - a.y*b.y, a.x*b.y + a.y*b.x);
}
// a * conj(b)
__device__ __forceinline__ float2 cmulj(float2 a, float2 b){
    return make_float2(a.x*b.x + a.y*b.y, a.y*b.x - a.x*b.y);
}

// ---------------------------------------------------------------------------
// Forward DIF FFT, 2048 points, radix-4 stages (h=512,128,32,8,2) + radix-2.
// Output is in a fixed (digit-reversed) permutation P: result = P * DFT(x).
// tw[k] = exp(-2*pi*i*k/2048), k in [0,512).
// ---------------------------------------------------------------------------
__device__ void fft_dif(float2* sb, const float2* tw, int tid)
{
#pragma unroll
    for (int s = 9; s >= 1; s -= 2) {
        int h = 1 << s;
        __syncthreads();
        int t   = tid & (h - 1);
        int blk = tid >> s;
        int i0  = (blk << (s + 2)) + t;
        float2 a = sb[i0], b = sb[i0 + h], c = sb[i0 + 2*h], d = sb[i0 + 3*h];
        float2 t0 = cadd(a, c);
        float2 t1 = csub(a, c);
        float2 t2 = cadd(b, d);
        float2 bd = csub(b, d);
        float2 t3 = make_float2(bd.y, -bd.x);          // -i*(b-d)
        float2 w1 = tw[t << (9 - s)];
        float2 w2 = cmul(w1, w1);
        float2 w3 = cmul(w2, w1);
        sb[i0]       = cadd(t0, t2);
        sb[i0 + h]   = cmul(cadd(t1, t3), w1);
        sb[i0 + 2*h] = cmul(csub(t0, t2), w2);
        sb[i0 + 3*h] = cmul(csub(t1, t3), w3);
    }
    // final radix-2 stage, h=1 (twiddle = 1)
    __syncthreads();
#pragma unroll
    for (int j = tid; j < 1024; j += NT) {
        int i0 = j << 1;
        float2 a = sb[i0], b = sb[i0 + 1];
        sb[i0]     = cadd(a, b);
        sb[i0 + 1] = csub(a, b);
    }
    __syncthreads();
}

// ---------------------------------------------------------------------------
// Exact inverse of fft_dif (stages inverted in reverse order, conj twiddles).
// Produces 2048 * IDFT(P^{-1} * input): the 1/2048 is deferred to the caller.
// ---------------------------------------------------------------------------
__device__ void ifft_dit(float2* sb, const float2* tw, int tid)
{
    // inverse of the radix-2 stage (same butterfly, scale deferred)
    __syncthreads();
#pragma unroll
    for (int j = tid; j < 1024; j += NT) {
        int i0 = j << 1;
        float2 a = sb[i0], b = sb[i0 + 1];
        sb[i0]     = cadd(a, b);
        sb[i0 + 1] = csub(a, b);
    }
#pragma unroll
    for (int s = 1; s <= 9; s += 2) {
        int h = 1 << s;
        __syncthreads();
        int t   = tid & (h - 1);
        int blk = tid >> s;
        int i0  = (blk << (s + 2)) + t;
        float2 w1 = tw[t << (9 - s)];
        float2 w2 = cmul(w1, w1);
        float2 w3 = cmul(w2, w1);
        float2 O0 = sb[i0];
        float2 O1 = cmulj(sb[i0 + h],   w1);
        float2 O2 = cmulj(sb[i0 + 2*h], w2);
        float2 O3 = cmulj(sb[i0 + 3*h], w3);
        float2 T0 = cadd(O0, O2);
        float2 T2 = csub(O0, O2);
        float2 T1 = cadd(O1, O3);
        float2 T3 = csub(O1, O3);
        float2 iT3 = make_float2(-T3.y, T3.x);         // i * T3
        sb[i0]       = cadd(T0, T1);
        sb[i0 + h]   = cadd(T2, iT3);
        sb[i0 + 2*h] = csub(T0, T1);
        sb[i0 + 3*h] = csub(T2, iT3);
    }
    __syncthreads();
}

__device__ __forceinline__ void init_tw(float2* tw, int tid)
{
    if (tid < 512) {
        float s, c;
        sincospif((float)tid * (1.0f / 1024.0f), &s, &c);
        tw[tid] = make_float2(c, -s);                  // exp(-2*pi*i*tid/2048)
    }
}

// ---------------------------------------------------------------------------
// Precompute: Ghat[i] = FFT(G[i]);  Hhat[i] = FFT(roll(reverse(H[i]*eta),1))
// blocks 0..3 -> G, blocks 4..7 -> H.  Same fft_dif => same permutation.
// ---------------------------------------------------------------------------
__global__ void __launch_bounds__(NT)
precompute_kernel(const float* __restrict__ G, const float* __restrict__ H)
{
    __shared__ float2 sb[NN];
    __shared__ float2 tw[512];
    int tid = threadIdx.x;
    init_tw(tw, tid);
    int wb = blockIdx.x;
    if (wb < RR) {
        const float* g = G + wb * NN;
        for (int k = tid; k < NN; k += NT)
            sb[k] = make_float2(g[k], 0.0f);
    } else {
        int i = wb - RR;
        const float* h = H + i * NN;
        for (int k = tid; k < NN; k += NT) {
            int j = (NN - k) & (NN - 1);               // Hm_rev[k] = Hm[(-k) mod n]
            float s, c;
            sincospif((float)j * (1.0f / (float)NN), &s, &c);   // eta_j
            float hv = h[j];
            sb[k] = make_float2(hv * c, hv * s);
        }
    }
    fft_dif(sb, tw, tid);
    float2* dst = (wb < RR) ? g_Ghat[wb] : g_Hhat[wb - RR];
    for (int k = tid; k < NN; k += NT)
        dst[k] = sb[k];
}

// ---------------------------------------------------------------------------
// Main kernel: one CTA per batch row.
// dynamic smem: sb[2048] | xhat[2048] | yhat[2048] | tw[512]  (52 KB)
// ---------------------------------------------------------------------------
__global__ void __launch_bounds__(NT)
toeplitz_kernel(const float* __restrict__ x, float* __restrict__ out)
{
    extern __shared__ float2 sm[];
    float2* sb = sm;
    float2* xh = sm + NN;
    float2* yh = sm + 2 * NN;
    float2* tw = sm + 3 * NN;

    int tid = threadIdx.x;
    init_tw(tw, tid);

    int row = blockIdx.x;
    const float* xr = x + (size_t)row * NN;

    // xm = x * conj(eta); also zero the Yhat accumulator
    for (int k = tid; k < NN; k += NT) {
        float s, c;
        sincospif((float)k * (1.0f / (float)NN), &s, &c);
        float v = xr[k];
        sb[k] = make_float2(v * c, -v * s);
        yh[k] = make_float2(0.0f, 0.0f);
    }

    fft_dif(sb, tw, tid);                              // Xhat (permuted)
    for (int k = tid; k < NN; k += NT) xh[k] = sb[k];

#pragma unroll 1
    for (int i = 0; i < RR; i++) {
        const float2* Hh = g_Hhat[i];
        for (int k = tid; k < NN; k += NT)
            sb[k] = cmul(Hh[k], xh[k]);                // A = Hhat .* Xhat

        ifft_dit(sb, tw, tid);                         // v = 2048*ifft(A), natural order

        for (int k = tid; k < NN; k += NT) {           // U = Re(eta*v)/2048
            float2 v = sb[k];
            float s, c;
            sincospif((float)k * (1.0f / (float)NN), &s, &c);
            float U = (v.x * c - v.y * s) * (1.0f / (float)NN);
            sb[k] = make_float2(U, 0.0f);
        }

        fft_dif(sb, tw, tid);                          // Uhat (permuted)

        const float2* Gh = g_Ghat[i];
        for (int k = tid; k < NN; k += NT) {
            float2 p = cmul(Gh[k], sb[k]);
            yh[k] = cadd(yh[k], p);                    // Yhat += Ghat .* Uhat
        }
    }

    for (int k = tid; k < NN; k += NT) sb[k] = yh[k];
    ifft_dit(sb, tw, tid);

    float* orow = out + (size_t)row * NN;
    for (int k = tid; k < NN; k += NT)
        orow[k] = sb[k].x * (1.0f / (float)NN);        // y = Re(ifft(Yhat))
}

// ---------------------------------------------------------------------------
extern "C" void kernel_launch(void* const* d_in, const int* in_sizes, int n_in,
                              void* d_out, int out_size)
{
    const float* x = (const float*)d_in[0];
    const float* G = (const float*)d_in[1];
    const float* H = (const float*)d_in[2];
    float* out = (float*)d_out;

    (void)in_sizes; (void)n_in; (void)out_size;

    size_t smem = (size_t)(3 * NN + 512) * sizeof(float2);   // 53248 B
    cudaFuncSetAttribute(toeplitz_kernel,
                         cudaFuncAttributeMaxDynamicSharedMemorySize, (int)smem);

    precompute_kernel<<<2 * RR, NT>>>(G, H);
    toeplitz_kernel<<<4096, NT, smem>>>(x, out);
}

// round 4
// speedup vs baseline: 1.4967x; 1.4967x over previous
#include <cuda_runtime.h>
#include <cuda_bf16.h>

#define NN   2048
#define RR   4
#define NT   512
#define IX(i) ((i) + ((i) >> 5))          // bank-conflict padding: +1 float2 per 32

// Precomputed (DIF-permuted-domain) filters, rebuilt each launch.
__device__ float2 g_Ghat[RR][NN];
__device__ float2 g_Hhat[RR][NN];
__device__ float2 g_HH[2][NN];            // Hhat_{2j} + i*Hhat_{2j+1}
__device__ float2 g_A [2][NN];            // (Ghat_{2j} - i*Ghat_{2j+1}) * 0.5/2048
__device__ float2 g_B [2][NN];            // (Ghat_{2j} + i*Ghat_{2j+1}) * 0.5/2048

__device__ __forceinline__ float2 cadd(float2 a, float2 b){ return make_float2(a.x+b.x, a.y+b.y); }
__device__ __forceinline__ float2 csub(float2 a, float2 b){ return make_float2(a.x-b.x, a.y-b.y); }
__device__ __forceinline__ float2 cmul(float2 a, float2 b){
    return make_float2(a.x*b.x - a.y*b.y, a.x*b.y + a.y*b.x);
}
__device__ __forceinline__ float2 cmulj(float2 a, float2 b){   // a * conj(b)
    return make_float2(a.x*b.x + a.y*b.y, a.y*b.x - a.x*b.y);
}

// σ: output position p of fft_dif holds frequency σ(p)  (radix-4^5 * 2 digit reversal)
__device__ __forceinline__ int sigma_p(int p){
    return ((p>>9)&3) | (((p>>7)&3)<<2) | (((p>>5)&3)<<4)
         | (((p>>3)&3)<<6) | (((p>>1)&3)<<8) | ((p&1)<<10);
}
__device__ __forceinline__ int sigma_inv(int k){
    return ((k&3)<<9) | (((k>>2)&3)<<7) | (((k>>4)&3)<<5)
         | (((k>>6)&3)<<3) | (((k>>8)&3)<<1) | ((k>>10)&1);
}
__device__ __forceinline__ int pair_idx(int p){
    return sigma_inv((NN - sigma_p(p)) & (NN - 1));
}

// ---------------------------------------------------------------------------
// Forward DIF FFT (2048 pts): radix-4 stages h=512,128,32,8,2 then radix-2.
// sb is IX-padded.  tw[k] = exp(-2*pi*i*k/2048), k in [0,512).
// ---------------------------------------------------------------------------
__device__ void fft_dif(float2* sb, const float2* tw, int tid)
{
#pragma unroll
    for (int s = 9; s >= 1; s -= 2) {
        int h = 1 << s;
        __syncthreads();
        int t   = tid & (h - 1);
        int blk = tid >> s;
        int i0  = (blk << (s + 2)) + t;
        float2 a = sb[IX(i0)], b = sb[IX(i0+h)], c = sb[IX(i0+2*h)], d = sb[IX(i0+3*h)];
        float2 t0 = cadd(a, c);
        float2 t1 = csub(a, c);
        float2 t2 = cadd(b, d);
        float2 bd = csub(b, d);
        float2 t3 = make_float2(bd.y, -bd.x);          // -i*(b-d)
        float2 w1 = tw[t << (9 - s)];
        float2 w2 = cmul(w1, w1);
        float2 w3 = cmul(w2, w1);
        sb[IX(i0)]       = cadd(t0, t2);
        sb[IX(i0+h)]     = cmul(cadd(t1, t3), w1);
        sb[IX(i0+2*h)]   = cmul(csub(t0, t2), w2);
        sb[IX(i0+3*h)]   = cmul(csub(t1, t3), w3);
    }
    __syncthreads();
#pragma unroll
    for (int j = tid; j < 1024; j += NT) {
        int i0 = j << 1;
        float2 a = sb[IX(i0)], b = sb[IX(i0+1)];
        sb[IX(i0)]   = cadd(a, b);
        sb[IX(i0+1)] = csub(a, b);
    }
    __syncthreads();
}

// Exact inverse of fft_dif (unscaled: returns 2048 * ifft), natural order out.
__device__ void ifft_dit(float2* sb, const float2* tw, int tid)
{
    __syncthreads();
#pragma unroll
    for (int j = tid; j < 1024; j += NT) {
        int i0 = j << 1;
        float2 a = sb[IX(i0)], b = sb[IX(i0+1)];
        sb[IX(i0)]   = cadd(a, b);
        sb[IX(i0+1)] = csub(a, b);
    }
#pragma unroll
    for (int s = 1; s <= 9; s += 2) {
        int h = 1 << s;
        __syncthreads();
        int t   = tid & (h - 1);
        int blk = tid >> s;
        int i0  = (blk << (s + 2)) + t;
        float2 w1 = tw[t << (9 - s)];
        float2 w2 = cmul(w1, w1);
        float2 w3 = cmul(w2, w1);
        float2 O0 = sb[IX(i0)];
        float2 O1 = cmulj(sb[IX(i0+h)],   w1);
        float2 O2 = cmulj(sb[IX(i0+2*h)], w2);
        float2 O3 = cmulj(sb[IX(i0+3*h)], w3);
        float2 T0 = cadd(O0, O2);
        float2 T2 = csub(O0, O2);
        float2 T1 = cadd(O1, O3);
        float2 T3 = csub(O1, O3);
        float2 iT3 = make_float2(-T3.y, T3.x);         // i*T3
        sb[IX(i0)]     = cadd(T0, T1);
        sb[IX(i0+h)]   = cadd(T2, iT3);
        sb[IX(i0+2*h)] = csub(T0, T1);
        sb[IX(i0+3*h)] = csub(T2, iT3);
    }
    __syncthreads();
}

__device__ __forceinline__ void init_tw(float2* tw, int tid)
{
    if (tid < 512) {
        float s, c;
        sincospif((float)tid * (1.0f / 1024.0f), &s, &c);
        tw[tid] = make_float2(c, -s);
    }
}

// ---------------------------------------------------------------------------
// Precompute raw spectra: blocks 0..3 -> Ghat, 4..7 -> Hhat (of roll/rev/eta'd H)
// ---------------------------------------------------------------------------
__global__ void __launch_bounds__(NT)
precompute_kernel(const float* __restrict__ G, const float* __restrict__ H)
{
    __shared__ float2 sb[IX(NN)];
    __shared__ float2 tw[512];
    int tid = threadIdx.x;
    init_tw(tw, tid);
    int wb = blockIdx.x;
    if (wb < RR) {
        const float* g = G + wb * NN;
        for (int k = tid; k < NN; k += NT)
            sb[IX(k)] = make_float2(g[k], 0.0f);
    } else {
        int i = wb - RR;
        const float* h = H + i * NN;
        for (int k = tid; k < NN; k += NT) {
            int j = (NN - k) & (NN - 1);
            float s, c;
            sincospif((float)j * (1.0f / (float)NN), &s, &c);
            float hv = h[j];
            sb[IX(k)] = make_float2(hv * c, hv * s);
        }
    }
    fft_dif(sb, tw, tid);
    float2* dst = (wb < RR) ? g_Ghat[wb] : g_Hhat[wb - RR];
    for (int k = tid; k < NN; k += NT)
        dst[k] = sb[IX(k)];
}

// Combine into packed filters HH / A / B (pointwise, per pair j = blockIdx.x)
__global__ void __launch_bounds__(NT)
combine_kernel()
{
    int j = blockIdx.x;
    int tid = threadIdx.x;
    const float cs = 0.5f / (float)NN;
    for (int k = tid; k < NN; k += NT) {
        float2 g0 = g_Ghat[2*j][k],  g1 = g_Ghat[2*j+1][k];
        float2 h0 = g_Hhat[2*j][k],  h1 = g_Hhat[2*j+1][k];
        g_A[j][k]  = make_float2((g0.x + g1.y) * cs, (g0.y - g1.x) * cs);
        g_B[j][k]  = make_float2((g0.x - g1.y) * cs, (g0.y + g1.x) * cs);
        g_HH[j][k] = make_float2(h0.x - h1.y,        h0.y + h1.x);
    }
}

// ---------------------------------------------------------------------------
// Main kernel: one CTA per batch row. 6 FFTs/row (was 10).
// smem: sb[2112] | yh[2112] | xh[2048] | tw[512]  = 54272 B
// ---------------------------------------------------------------------------
__global__ void __launch_bounds__(NT)
toeplitz_kernel(const float* __restrict__ x, float* __restrict__ out)
{
    extern __shared__ float2 sm[];
    float2* sb = sm;                       // 2112 (padded)
    float2* yh = sm + IX(NN);              // 2112 (padded)
    float2* xh = sm + 2 * IX(NN);          // 2048
    float2* tw = sm + 2 * IX(NN) + NN;     // 512

    int tid = threadIdx.x;
    init_tw(tw, tid);

    int row = blockIdx.x;
    const float* xr = x + (size_t)row * NN;

    // xm = x * conj(eta); zero Yhat accumulator
    for (int k = tid; k < IX(NN); k += NT) yh[k] = make_float2(0.f, 0.f);
    for (int k = tid; k < NN; k += NT) {
        float s, c;
        sincospif((float)k * (1.0f / (float)NN), &s, &c);
        float v = xr[k];
        sb[IX(k)] = make_float2(v * c, -v * s);
    }

    fft_dif(sb, tw, tid);                              // Xhat (permuted)
    for (int k = tid; k < NN; k += NT) xh[k] = sb[IX(k)];
    __syncthreads();

#pragma unroll 1
    for (int j = 0; j < 2; j++) {
        const float2* __restrict__ HH = g_HH[j];
        for (int k = tid; k < NN; k += NT)
            sb[IX(k)] = cmul(HH[k], xh[k]);            // T = HH .* Xhat

        ifft_dit(sb, tw, tid);                         // 2048*ifft(T)

        for (int k = tid; k < NN; k += NT) {           // z' = eta .* v (packed U0+iU1)
            float s, c;
            sincospif((float)k * (1.0f / (float)NN), &s, &c);
            sb[IX(k)] = cmul(make_float2(c, s), sb[IX(k)]);
        }

        fft_dif(sb, tw, tid);                          // What' (permuted)

        const float2* __restrict__ A = g_A[j];
        const float2* __restrict__ B = g_B[j];
        for (int p = tid; p < NN; p += NT) {           // Yhat += A.*W + B.*conj(W o neg)
            int q = pair_idx(p);
            float2 w  = sb[IX(p)];
            float2 wq = sb[IX(q)];
            float2 acc = yh[IX(p)];
            acc = cadd(acc, cmul(A[p], w));
            acc = cadd(acc, cmulj(B[p], wq));          // B * conj(W[neg])  (FIXED)
            yh[IX(p)] = acc;
        }
        __syncthreads();
    }

    ifft_dit(yh, tw, tid);

    float* orow = out + (size_t)row * NN;
    for (int k = tid; k < NN; k += NT)
        orow[k] = yh[IX(k)].x * (1.0f / (float)NN);
}

// ---------------------------------------------------------------------------
extern "C" void kernel_launch(void* const* d_in, const int* in_sizes, int n_in,
                              void* d_out, int out_size)
{
    const float* x = (const float*)d_in[0];
    const float* G = (const float*)d_in[1];
    const float* H = (const float*)d_in[2];
    float* out = (float*)d_out;
    (void)in_sizes; (void)n_in; (void)out_size;

    size_t smem = (size_t)(2 * IX(NN) + NN + 512) * sizeof(float2);   // 54272 B
    cudaFuncSetAttribute(toeplitz_kernel,
                         cudaFuncAttributeMaxDynamicSharedMemorySize, (int)smem);

    precompute_kernel<<<2 * RR, NT>>>(G, H);
    combine_kernel<<<2, NT>>>();
    toeplitz_kernel<<<4096, NT, smem>>>(x, out);
}

// round 5
// speedup vs baseline: 2.3655x; 1.5804x over previous
#include <cuda_runtime.h>
#include <cuda_bf16.h>

#define NN   2048
#define RR   4
#define NT   256
#define SMN  2080                       // 65 * 32 padded matrix
#define IX64(i) ((i) + ((i) >> 6))      // linear (p1 + 64*p2) -> padded (p1 + 65*p2)

// Precomputed filters (linear storage index), rebuilt each launch.
__device__ float2 g_Ghat[RR][NN];
__device__ float2 g_Hhat[RR][NN];
__device__ float2 g_HH[2][NN];          // Hhat_{2j} + i*Hhat_{2j+1}
__device__ float2 g_A [2][NN];          // (Ghat_{2j} - i*Ghat_{2j+1}) * 0.5/2048
__device__ float2 g_B [2][NN];          // (Ghat_{2j} + i*Ghat_{2j+1}) * 0.5/2048

__device__ __forceinline__ float2 cadd(float2 a, float2 b){ return make_float2(a.x+b.x, a.y+b.y); }
__device__ __forceinline__ float2 csub(float2 a, float2 b){ return make_float2(a.x-b.x, a.y-b.y); }
__device__ __forceinline__ float2 cmul(float2 a, float2 b){
    return make_float2(a.x*b.x - a.y*b.y, a.x*b.y + a.y*b.x);
}
__device__ __forceinline__ float2 cmulj(float2 a, float2 b){   // a * conj(b)
    return make_float2(a.x*b.x + a.y*b.y, a.y*b.x - a.x*b.y);
}
__device__ __forceinline__ float2 csqr(float2 a){ return make_float2(a.x*a.x - a.y*a.y, 2.f*a.x*a.y); }
__device__ __forceinline__ float2 cneg(float2 a){ return make_float2(-a.x, -a.y); }
__device__ __forceinline__ int br5(int x){ return (int)(__brev((unsigned)x) >> 27); }

__device__ __forceinline__ float2 shfl_xor_c(float2 v, int m){
    return make_float2(__shfl_xor_sync(0xffffffffu, v.x, m),
                       __shfl_xor_sync(0xffffffffu, v.y, m));
}

// Per-lane register twiddles (computed once per thread).
struct LaneTw {
    float2 w16, w8, w4;    // FFT-32 stage twiddles: exp(-pi*i*(l&(h-1))/h)
    float2 wB;             // exp(-pi*i*lane/32) for FFT-64 first stage
    float2 colT0;          // exp(-2pi*i * warp * br5(lane) / 2048)
    float2 colStep;        // exp(-2pi*i * 8    * br5(lane) / 2048)
};

__device__ __forceinline__ LaneTw make_tw(int lane, int w){
    LaneTw T; float s, c;
    sincospif((float)(lane & 15) * (1.f/16.f), &s, &c);
    T.w16 = make_float2(c, -s);
    T.w8 = csqr(T.w16); if (lane & 8) T.w8 = cneg(T.w8);
    T.w4 = csqr(T.w8);  if (lane & 4) T.w4 = cneg(T.w4);
    sincospif((float)lane * (1.f/32.f), &s, &c);
    T.wB = make_float2(c, -s);
    int b = br5(lane);
    sincospif((float)(w * b) * (1.f/1024.f), &s, &c);
    T.colT0 = make_float2(c, -s);
    sincospif((float)b * (1.f/128.f), &s, &c);
    T.colStep = make_float2(c, -s);
    return T;
}

// DIF FFT-32 across lanes; input natural (lane = time), output lane l holds X[br5(l)].
__device__ __forceinline__ float2 fft32_fwd(float2 v, const LaneTw& T, int lane){
    float2 p, d;
    p = shfl_xor_c(v, 16);
    v = (lane & 16) ? cmul(csub(p, v), T.w16) : cadd(v, p);
    p = shfl_xor_c(v, 8);
    v = (lane & 8)  ? cmul(csub(p, v), T.w8)  : cadd(v, p);
    p = shfl_xor_c(v, 4);
    v = (lane & 4)  ? cmul(csub(p, v), T.w4)  : cadd(v, p);
    p = shfl_xor_c(v, 2);                          // w = 1 or -i
    if (lane & 2) { d = csub(p, v); v = (lane & 1) ? make_float2(d.y, -d.x) : d; }
    else            v = cadd(v, p);
    p = shfl_xor_c(v, 1);                          // w = 1
    v = (lane & 1) ? csub(p, v) : cadd(v, p);
    return v;
}

// Exact unscaled inverse of fft32_fwd (input bit-reversed, output natural, x32).
__device__ __forceinline__ float2 fft32_inv(float2 v, const LaneTw& T, int lane){
    float2 p;
    p = shfl_xor_c(v, 1);
    v = (lane & 1) ? csub(p, v) : cadd(v, p);
    if ((lane & 2) && (lane & 1)) v = make_float2(-v.y, v.x);   // * conj(-i) = *i
    p = shfl_xor_c(v, 2);
    v = (lane & 2) ? csub(p, v) : cadd(v, p);
    if (lane & 4)  v = cmulj(v, T.w4);
    p = shfl_xor_c(v, 4);
    v = (lane & 4) ? csub(p, v) : cadd(v, p);
    if (lane & 8)  v = cmulj(v, T.w8);
    p = shfl_xor_c(v, 8);
    v = (lane & 8) ? csub(p, v) : cadd(v, p);
    if (lane & 16) v = cmulj(v, T.w16);
    p = shfl_xor_c(v, 16);
    v = (lane & 16) ? csub(p, v) : cadd(v, p);
    return v;
}

// Forward 2048-pt transform on padded smem matrix m (addr = p1 + 65*p2).
// Input: natural time n = p1 + 64*p2.  Output: position (p1,p2) holds
// frequency k = 32*kappa(p1) + br5(p2), kappa(p1) = 2*br5(p1&31) + (p1>>5).
__device__ void fft2048_fwd(float2* m, const LaneTw& T, int lane, int w){
    __syncthreads();
    float2 colT = T.colT0;
#pragma unroll
    for (int j = 0; j < 8; j++){                   // Step A: FFT-32 over n2
        int a = (w + 8*j) + 65*lane;
        float2 v = m[a];
        v = fft32_fwd(v, T, lane);
        v = cmul(v, colT);                          // * exp(-2pi i n1 br5(lane)/2048)
        m[a] = v;
        colT = cmul(colT, T.colStep);
    }
    __syncthreads();
#pragma unroll
    for (int j = 0; j < 4; j++){                   // Step B: FFT-64 over n1
        int a = lane + 65*(w + 8*j);
        float2 e0 = m[a], e1 = m[a+32];
        float2 u = e0;
        e0 = cadd(u, e1);
        e1 = cmul(csub(u, e1), T.wB);
        e0 = fft32_fwd(e0, T, lane);
        e1 = fft32_fwd(e1, T, lane);
        m[a] = e0; m[a+32] = e1;
    }
    __syncthreads();
}

// Exact inverse (unscaled: x2048), natural time order out.
__device__ void fft2048_inv(float2* m, const LaneTw& T, int lane, int w){
    __syncthreads();
#pragma unroll
    for (int j = 0; j < 4; j++){                   // Step B^-1
        int a = lane + 65*(w + 8*j);
        float2 e0 = m[a], e1 = m[a+32];
        e0 = fft32_inv(e0, T, lane);
        e1 = fft32_inv(e1, T, lane);
        float2 t1 = cmulj(e1, T.wB);
        e1 = csub(e0, t1);
        e0 = cadd(e0, t1);
        m[a] = e0; m[a+32] = e1;
    }
    __syncthreads();
    float2 colT = T.colT0;
#pragma unroll
    for (int j = 0; j < 8; j++){                   // Step A^-1
        int a = (w + 8*j) + 65*lane;
        float2 v = m[a];
        v = cmulj(v, colT);
        v = fft32_inv(v, T, lane);
        m[a] = v;
        colT = cmul(colT, T.colStep);
    }
    __syncthreads();
}

// linear storage idx of frequency -k, given linear idx of frequency k
__device__ __forceinline__ int pair_lin(int idx){
    int p1 = idx & 63, p2 = idx >> 6;
    int k1 = 2*br5(p1 & 31) + (p1 >> 5);
    int k2 = br5(p2);
    int k1n, k2n;
    if (k2 == 0){ k2n = 0;       k1n = (64 - k1) & 63; }
    else        { k2n = 32 - k2; k1n = 63 - k1; }
    int p1n = ((k1n & 1) << 5) + br5(k1n >> 1);
    return p1n + 64 * br5(k2n & 31);
}

// ---------------------------------------------------------------------------
__global__ void __launch_bounds__(NT)
precompute_kernel(const float* __restrict__ G, const float* __restrict__ H)
{
    __shared__ float2 m[SMN];
    int tid = threadIdx.x, lane = tid & 31, w = tid >> 5;
    LaneTw T = make_tw(lane, w);
    int wb = blockIdx.x;
    if (wb < RR){
        const float* g = G + wb * NN;
        for (int k = tid; k < NN; k += NT)
            m[IX64(k)] = make_float2(g[k], 0.f);
    } else {
        const float* h = H + (wb - RR) * NN;
        for (int k = tid; k < NN; k += NT){
            int j = (NN - k) & (NN - 1);
            float s, c;
            sincospif((float)j * (1.f/(float)NN), &s, &c);
            float hv = h[j];
            m[IX64(k)] = make_float2(hv * c, hv * s);
        }
    }
    fft2048_fwd(m, T, lane, w);
    float2* dst = (wb < RR) ? g_Ghat[wb] : g_Hhat[wb - RR];
    for (int k = tid; k < NN; k += NT) dst[k] = m[IX64(k)];
}

__global__ void __launch_bounds__(NT)
combine_kernel()
{
    int j = blockIdx.x, tid = threadIdx.x;
    const float cs = 0.5f / (float)NN;
    for (int k = tid; k < NN; k += NT){
        float2 g0 = g_Ghat[2*j][k], g1 = g_Ghat[2*j+1][k];
        float2 h0 = g_Hhat[2*j][k], h1 = g_Hhat[2*j+1][k];
        g_A[j][k]  = make_float2((g0.x + g1.y) * cs, (g0.y - g1.x) * cs);
        g_B[j][k]  = make_float2((g0.x - g1.y) * cs, (g0.y + g1.x) * cs);
        g_HH[j][k] = make_float2(h0.x - h1.y,        h0.y + h1.x);
    }
}

// ---------------------------------------------------------------------------
// Main: one CTA per batch row. smem = m | xh | yh (3 * 2080 float2 = 49,920 B)
// ---------------------------------------------------------------------------
__global__ void __launch_bounds__(NT, 4)
toeplitz_kernel(const float* __restrict__ x, float* __restrict__ out)
{
    extern __shared__ float2 sm[];
    float2* m  = sm;
    float2* xh = sm + SMN;
    float2* yh = sm + 2*SMN;

    int tid = threadIdx.x, lane = tid & 31, w = tid >> 5;
    LaneTw T = make_tw(lane, w);
    const float* xr = x + (size_t)blockIdx.x * NN;

    for (int idx = tid; idx < NN; idx += NT){
        float s, c;
        sincospif((float)idx * (1.f/(float)NN), &s, &c);
        float v = xr[idx];
        int a = IX64(idx);
        m[a]  = make_float2(v * c, -v * s);        // x * conj(eta)
        yh[a] = make_float2(0.f, 0.f);
    }

    fft2048_fwd(m, T, lane, w);                    // Xhat (permuted)
    for (int a = tid; a < SMN; a += NT) xh[a] = m[a];
    __syncthreads();

#pragma unroll 1
    for (int jj = 0; jj < 2; jj++){
        const float2* __restrict__ HH = g_HH[jj];
        for (int idx = tid; idx < NN; idx += NT){
            int a = IX64(idx);
            m[a] = cmul(HH[idx], xh[a]);           // T = HH .* Xhat
        }
        fft2048_inv(m, T, lane, w);                // 2048 * ifft(T), natural
        for (int idx = tid; idx < NN; idx += NT){  // z = eta .* v  (packed U0+iU1)
            float s, c;
            sincospif((float)idx * (1.f/(float)NN), &s, &c);
            int a = IX64(idx);
            m[a] = cmul(make_float2(c, s), m[a]);
        }
        fft2048_fwd(m, T, lane, w);                // What (permuted)

        const float2* __restrict__ A = g_A[jj];
        const float2* __restrict__ B = g_B[jj];
        for (int idx = tid; idx < NN; idx += NT){  // Yhat += A.*W + B.*conj(W o neg)
            int q = pair_lin(idx);
            float2 wv = m[IX64(idx)];
            float2 wq = m[IX64(q)];
            int a = IX64(idx);
            yh[a] = cadd(yh[a], cadd(cmul(A[idx], wv), cmulj(B[idx], wq)));
        }
        __syncthreads();
    }

    fft2048_inv(yh, T, lane, w);

    float* orow = out + (size_t)blockIdx.x * NN;
    for (int idx = tid; idx < NN; idx += NT)
        orow[idx] = yh[IX64(idx)].x * (1.f/(float)NN);
}

// ---------------------------------------------------------------------------
extern "C" void kernel_launch(void* const* d_in, const int* in_sizes, int n_in,
                              void* d_out, int out_size)
{
    const float* x = (const float*)d_in[0];
    const float* G = (const float*)d_in[1];
    const float* H = (const float*)d_in[2];
    float* out = (float*)d_out;
    (void)in_sizes; (void)n_in; (void)out_size;

    size_t smem = (size_t)(3 * SMN) * sizeof(float2);   // 49,920 B
    cudaFuncSetAttribute(toeplitz_kernel,
                         cudaFuncAttributeMaxDynamicSharedMemorySize, (int)smem);

    precompute_kernel<<<2 * RR, NT>>>(G, H);
    combine_kernel<<<2, NT>>>();
    toeplitz_kernel<<<4096, NT, smem>>>(x, out);
}

// round 6
// speedup vs baseline: 2.4065x; 1.0174x over previous
#include <cuda_runtime.h>
#include <cuda_bf16.h>

#define NN   2048
#define RR   4
#define NT   256
#define SMN  2080                       // 65 * 32 padded matrix
#define IX64(i) ((i) + ((i) >> 6))      // linear (p1 + 64*p2) -> padded (p1 + 65*p2)

// Precomputed filters (linear storage index), rebuilt each launch.
__device__ float2 g_Ghat[RR][NN];
__device__ float2 g_Hhat[RR][NN];
__device__ float2 g_HH[2][NN];          // Hhat_{2j} + i*Hhat_{2j+1}
__device__ float2 g_A [2][NN];          // (Ghat_{2j} - i*Ghat_{2j+1}) * 0.5/2048
__device__ float2 g_B [2][NN];          // (Ghat_{2j} + i*Ghat_{2j+1}) * 0.5/2048

__device__ __forceinline__ float2 cadd(float2 a, float2 b){ return make_float2(a.x+b.x, a.y+b.y); }
__device__ __forceinline__ float2 csub(float2 a, float2 b){ return make_float2(a.x-b.x, a.y-b.y); }
__device__ __forceinline__ float2 cmul(float2 a, float2 b){
    return make_float2(a.x*b.x - a.y*b.y, a.x*b.y + a.y*b.x);
}
__device__ __forceinline__ float2 cmulj(float2 a, float2 b){   // a * conj(b)
    return make_float2(a.x*b.x + a.y*b.y, a.y*b.x - a.x*b.y);
}
__device__ __forceinline__ float2 csqr(float2 a){ return make_float2(a.x*a.x - a.y*a.y, 2.f*a.x*a.y); }
__device__ __forceinline__ float2 cneg(float2 a){ return make_float2(-a.x, -a.y); }
__device__ __forceinline__ int br5(int x){ return (int)(__brev((unsigned)x) >> 27); }

__device__ __forceinline__ float2 shfl_xor_c(float2 v, int m){
    return make_float2(__shfl_xor_sync(0xffffffffu, v.x, m),
                       __shfl_xor_sync(0xffffffffu, v.y, m));
}

struct LaneTw {
    float2 w16, w8, w4;    // FFT-32 stage twiddles
    float2 wB;             // exp(-pi*i*lane/32)
    float2 colT0;          // exp(-2pi*i * w * br5(lane) / 2048)
    float2 colStep;        // exp(-2pi*i * 8 * br5(lane) / 2048)
};

__device__ __forceinline__ LaneTw make_tw(int lane, int w){
    LaneTw T; float s, c;
    sincospif((float)(lane & 15) * (1.f/16.f), &s, &c);
    T.w16 = make_float2(c, -s);
    T.w8 = csqr(T.w16); if (lane & 8) T.w8 = cneg(T.w8);
    T.w4 = csqr(T.w8);  if (lane & 4) T.w4 = cneg(T.w4);
    sincospif((float)lane * (1.f/32.f), &s, &c);
    T.wB = make_float2(c, -s);
    int b = br5(lane);
    sincospif((float)(w * b) * (1.f/1024.f), &s, &c);
    T.colT0 = make_float2(c, -s);
    sincospif((float)b * (1.f/128.f), &s, &c);
    T.colStep = make_float2(c, -s);
    return T;
}

// DIF FFT-32 across lanes; input natural (lane = time), output lane l holds X[br5(l)].
__device__ __forceinline__ float2 fft32_fwd(float2 v, const LaneTw& T, int lane){
    float2 p, d;
    p = shfl_xor_c(v, 16);
    v = (lane & 16) ? cmul(csub(p, v), T.w16) : cadd(v, p);
    p = shfl_xor_c(v, 8);
    v = (lane & 8)  ? cmul(csub(p, v), T.w8)  : cadd(v, p);
    p = shfl_xor_c(v, 4);
    v = (lane & 4)  ? cmul(csub(p, v), T.w4)  : cadd(v, p);
    p = shfl_xor_c(v, 2);
    if (lane & 2) { d = csub(p, v); v = (lane & 1) ? make_float2(d.y, -d.x) : d; }
    else            v = cadd(v, p);
    p = shfl_xor_c(v, 1);
    v = (lane & 1) ? csub(p, v) : cadd(v, p);
    return v;
}

// Exact unscaled inverse of fft32_fwd (input bit-reversed, output natural, x32).
__device__ __forceinline__ float2 fft32_inv(float2 v, const LaneTw& T, int lane){
    float2 p;
    p = shfl_xor_c(v, 1);
    v = (lane & 1) ? csub(p, v) : cadd(v, p);
    if ((lane & 2) && (lane & 1)) v = make_float2(-v.y, v.x);
    p = shfl_xor_c(v, 2);
    v = (lane & 2) ? csub(p, v) : cadd(v, p);
    if (lane & 4)  v = cmulj(v, T.w4);
    p = shfl_xor_c(v, 4);
    v = (lane & 4) ? csub(p, v) : cadd(v, p);
    if (lane & 8)  v = cmulj(v, T.w8);
    p = shfl_xor_c(v, 8);
    v = (lane & 8) ? csub(p, v) : cadd(v, p);
    if (lane & 16) v = cmulj(v, T.w16);
    p = shfl_xor_c(v, 16);
    v = (lane & 16) ? csub(p, v) : cadd(v, p);
    return v;
}

// Full forward 2048-pt transform in smem (used by precompute only).
__device__ void fft2048_fwd(float2* m, const LaneTw& T, int lane, int w){
    __syncthreads();
    float2 colT = T.colT0;
#pragma unroll
    for (int j = 0; j < 8; j++){
        int a = (w + 8*j) + 65*lane;
        float2 v = m[a];
        v = fft32_fwd(v, T, lane);
        m[a] = cmul(v, colT);
        colT = cmul(colT, T.colStep);
    }
    __syncthreads();
#pragma unroll
    for (int j = 0; j < 4; j++){
        int a = lane + 65*(w + 8*j);
        float2 e0 = m[a], e1 = m[a+32];
        float2 u = e0;
        e0 = cadd(u, e1);
        e1 = cmul(csub(u, e1), T.wB);
        m[a] = fft32_fwd(e0, T, lane);
        m[a+32] = fft32_fwd(e1, T, lane);
    }
    __syncthreads();
}

// linear storage idx of frequency -k, given linear idx of frequency k
__device__ __forceinline__ int pair_lin(int idx){
    int p1 = idx & 63, p2 = idx >> 6;
    int k1 = 2*br5(p1 & 31) + (p1 >> 5);
    int k2 = br5(p2);
    int k1n, k2n;
    if (k2 == 0){ k2n = 0;       k1n = (64 - k1) & 63; }
    else        { k2n = 32 - k2; k1n = 63 - k1; }
    int p1n = ((k1n & 1) << 5) + br5(k1n >> 1);
    return p1n + 64 * br5(k2n & 31);
}

// ---------------------------------------------------------------------------
__global__ void __launch_bounds__(NT)
precompute_kernel(const float* __restrict__ G, const float* __restrict__ H)
{
    __shared__ float2 m[SMN];
    int tid = threadIdx.x, lane = tid & 31, w = tid >> 5;
    LaneTw T = make_tw(lane, w);
    int wb = blockIdx.x;
    if (wb < RR){
        const float* g = G + wb * NN;
        for (int k = tid; k < NN; k += NT)
            m[IX64(k)] = make_float2(g[k], 0.f);
    } else {
        const float* h = H + (wb - RR) * NN;
        for (int k = tid; k < NN; k += NT){
            int j = (NN - k) & (NN - 1);
            float s, c;
            sincospif((float)j * (1.f/(float)NN), &s, &c);
            float hv = h[j];
            m[IX64(k)] = make_float2(hv * c, hv * s);
        }
    }
    fft2048_fwd(m, T, lane, w);
    float2* dst = (wb < RR) ? g_Ghat[wb] : g_Hhat[wb - RR];
    for (int k = tid; k < NN; k += NT) dst[k] = m[IX64(k)];
}

__global__ void __launch_bounds__(NT)
combine_kernel()
{
    int j = blockIdx.x, tid = threadIdx.x;
    const float cs = 0.5f / (float)NN;
    for (int k = tid; k < NN; k += NT){
        float2 g0 = g_Ghat[2*j][k], g1 = g_Ghat[2*j+1][k];
        float2 h0 = g_Hhat[2*j][k], h1 = g_Hhat[2*j+1][k];
        g_A[j][k]  = make_float2((g0.x + g1.y) * cs, (g0.y - g1.x) * cs);
        g_B[j][k]  = make_float2((g0.x - g1.y) * cs, (g0.y + g1.x) * cs);
        g_HH[j][k] = make_float2(h0.x - h1.y,        h0.y + h1.x);
    }
}

// ---------------------------------------------------------------------------
// Main: one CTA per batch row. Single smem buffer m (2080 float2 = 16,640 B).
// Xhat and Yhat live entirely in registers.
// ---------------------------------------------------------------------------
__global__ void __launch_bounds__(NT)
toeplitz_kernel(const float* __restrict__ x, float* __restrict__ out)
{
    __shared__ float2 m[SMN];

    int tid = threadIdx.x, lane = tid & 31, w = tid >> 5;
    LaneTw T = make_tw(lane, w);

    // eta for the column pattern: idx = (w + 8j) + 64*lane
    float2 etaBase;
    {
        float s, c;
        sincospif((float)(w + 64*lane) * (1.f/2048.f), &s, &c);
        etaBase = make_float2(c, s);
    }
    const float2 ETA_STEP = make_float2(0.9999247018391445f, 0.012271538285719925f); // e^{i*pi/256}

    const float* xr = x + (size_t)blockIdx.x * NN;

    // ---- load: x * conj(eta), natural order ----
    for (int idx = tid; idx < NN; idx += NT){
        float s, c;
        sincospif((float)idx * (1.f/(float)NN), &s, &c);
        float v = xr[idx];
        m[IX64(idx)] = make_float2(v * c, -v * s);
    }
    __syncthreads();

    // ---- fwd Step A (cols) ----
    {
        float2 colT = T.colT0;
#pragma unroll
        for (int j = 0; j < 8; j++){
            int a = (w + 8*j) + 65*lane;
            float2 v = fft32_fwd(m[a], T, lane);
            m[a] = cmul(v, colT);
            colT = cmul(colT, T.colStep);
        }
    }
    __syncthreads();

    // ---- fwd Step B (rows) -> Xhat stays in registers ----
    float2 xh0[4], xh1[4];
#pragma unroll
    for (int j = 0; j < 4; j++){
        int a = lane + 65*(w + 8*j);
        float2 e0 = m[a], e1 = m[a+32];
        float2 u = e0;
        e0 = cadd(u, e1);
        e1 = cmul(csub(u, e1), T.wB);
        xh0[j] = fft32_fwd(e0, T, lane);
        xh1[j] = fft32_fwd(e1, T, lane);
    }

    float2 y0[4], y1[4];
#pragma unroll
    for (int j = 0; j < 4; j++){ y0[j] = make_float2(0.f,0.f); y1[j] = make_float2(0.f,0.f); }

#pragma unroll 1
    for (int jj = 0; jj < 2; jj++){
        const float2* __restrict__ HH = g_HH[jj];
        const float2* __restrict__ A  = g_A[jj];
        const float2* __restrict__ B  = g_B[jj];

        __syncthreads();                 // m free of pending reads (gather of prev iter)
        // ---- T = HH .* Xhat, Step B^-1, write rows ----
#pragma unroll
        for (int j = 0; j < 4; j++){
            int idx0 = lane + 64*(w + 8*j);
            float2 e0 = cmul(HH[idx0],      xh0[j]);
            float2 e1 = cmul(HH[idx0 + 32], xh1[j]);
            e0 = fft32_inv(e0, T, lane);
            e1 = fft32_inv(e1, T, lane);
            float2 t1 = cmulj(e1, T.wB);
            int a = lane + 65*(w + 8*j);
            m[a]    = cadd(e0, t1);
            m[a+32] = csub(e0, t1);
        }
        __syncthreads();

        // ---- cols: Step A^-1, eta multiply, Step A fwd (fully fused) ----
        {
            float2 colT = T.colT0;
            float2 eta  = etaBase;
#pragma unroll
            for (int j = 0; j < 8; j++){
                int a = (w + 8*j) + 65*lane;
                float2 v = cmulj(m[a], colT);
                v = fft32_inv(v, T, lane);
                v = cmul(eta, v);                 // packed z = eta .* ifft
                v = fft32_fwd(v, T, lane);
                m[a] = cmul(v, colT);
                colT = cmul(colT, T.colStep);
                eta  = cmul(eta, ETA_STEP);
            }
        }
        __syncthreads();

        // ---- rows: Step B fwd -> W (regs) ; also write W for pair gather ----
        float2 w0[4], w1[4];
#pragma unroll
        for (int j = 0; j < 4; j++){
            int a = lane + 65*(w + 8*j);
            float2 e0 = m[a], e1 = m[a+32];
            float2 u = e0;
            e0 = cadd(u, e1);
            e1 = cmul(csub(u, e1), T.wB);
            w0[j] = fft32_fwd(e0, T, lane);
            w1[j] = fft32_fwd(e1, T, lane);
            m[a]    = w0[j];
            m[a+32] = w1[j];
        }
        __syncthreads();

        // ---- accumulate Yhat (regs): A.*W + B.*conj(W o neg) ----
#pragma unroll
        for (int j = 0; j < 4; j++){
            int idx0 = lane + 64*(w + 8*j);
            int idx1 = idx0 + 32;
            int q0 = pair_lin(idx0);
            int q1 = pair_lin(idx1);
            y0[j] = cadd(y0[j], cadd(cmul(A[idx0], w0[j]), cmulj(B[idx0], m[IX64(q0)])));
            y1[j] = cadd(y1[j], cadd(cmul(A[idx1], w1[j]), cmulj(B[idx1], m[IX64(q1)])));
        }
    }

    // ---- final inverse FFT of Yhat: Step B^-1 from registers ----
    __syncthreads();
#pragma unroll
    for (int j = 0; j < 4; j++){
        float2 e0 = fft32_inv(y0[j], T, lane);
        float2 e1 = fft32_inv(y1[j], T, lane);
        float2 t1 = cmulj(e1, T.wB);
        int a = lane + 65*(w + 8*j);
        m[a]    = cadd(e0, t1);
        m[a+32] = csub(e0, t1);
    }
    __syncthreads();

    // ---- Step A^-1 into registers ----
    float2 res[8];
    {
        float2 colT = T.colT0;
#pragma unroll
        for (int j = 0; j < 8; j++){
            int a = (w + 8*j) + 65*lane;
            res[j] = fft32_inv(cmulj(m[a], colT), T, lane);
            colT = cmul(colT, T.colStep);
        }
    }
    __syncthreads();                      // all float2 reads done before float overwrite

    // ---- stage real parts (conflict-free) then coalesced gmem store ----
    float* fo = (float*)m;
#pragma unroll
    for (int j = 0; j < 8; j++)
        fo[(w + 8*j) + 65*lane] = res[j].x * (1.f/(float)NN);
    __syncthreads();

    float* orow = out + (size_t)blockIdx.x * NN;
    for (int idx = tid; idx < NN; idx += NT)
        orow[idx] = fo[IX64(idx)];
}

// ---------------------------------------------------------------------------
extern "C" void kernel_launch(void* const* d_in, const int* in_sizes, int n_in,
                              void* d_out, int out_size)
{
    const float* x = (const float*)d_in[0];
    const float* G = (const float*)d_in[1];
    const float* H = (const float*)d_in[2];
    float* out = (float*)d_out;
    (void)in_sizes; (void)n_in; (void)out_size;

    precompute_kernel<<<2 * RR, NT>>>(G, H);
    combine_kernel<<<2, NT>>>();
    toeplitz_kernel<<<4096, NT>>>(x, out);
}

// round 7
// speedup vs baseline: 3.3317x; 1.3845x over previous
#include <cuda_runtime.h>
#include <cuda_bf16.h>

#define NN 2048
#define RR 4
#define NT 256
#define BR3(j) ((((j)&1)<<2) | ((j)&2) | (((j)&4)>>2))

// Precomputed filters, storage index fidx = 256v + 32s + c  (k = 256v + 8c + s)
__device__ float2 g_Ghat[RR][NN];
__device__ float2 g_Hhat[RR][NN];
__device__ float2 g_HH[2][NN];
__device__ float2 g_A [2][NN];
__device__ float2 g_B [2][NN];

__device__ __forceinline__ float2 cadd(float2 a, float2 b){ return make_float2(a.x+b.x, a.y+b.y); }
__device__ __forceinline__ float2 csub(float2 a, float2 b){ return make_float2(a.x-b.x, a.y-b.y); }
__device__ __forceinline__ float2 cmul(float2 a, float2 b){
    return make_float2(a.x*b.x - a.y*b.y, a.x*b.y + a.y*b.x);
}
__device__ __forceinline__ float2 cmulj(float2 a, float2 b){   // a * conj(b)
    return make_float2(a.x*b.x + a.y*b.y, a.y*b.x - a.x*b.y);
}
__device__ __forceinline__ float2 csqr(float2 a){ return make_float2(a.x*a.x - a.y*a.y, 2.f*a.x*a.y); }
__device__ __forceinline__ float2 cneg(float2 a){ return make_float2(-a.x, -a.y); }
__device__ __forceinline__ int br5(int x){ return (int)(__brev((unsigned)x) >> 27); }

__device__ __forceinline__ float2 shfl_xor_c(float2 v, int m){
    return make_float2(__shfl_xor_sync(0xffffffffu, v.x, m),
                       __shfl_xor_sync(0xffffffffu, v.y, m));
}

struct LaneTw { float2 w16, w8, w4; };

__device__ __forceinline__ LaneTw make_lane_tw(int lane){
    LaneTw T; float s, c;
    sincospif((float)(lane & 15) * (1.f/16.f), &s, &c);
    T.w16 = make_float2(c, -s);
    T.w8 = csqr(T.w16); if (lane & 8) T.w8 = cneg(T.w8);
    T.w4 = csqr(T.w8);  if (lane & 4) T.w4 = cneg(T.w4);
    return T;
}

// DIF FFT-32 across lanes; input natural (lane = time), output lane l holds X[br5(l)].
__device__ __forceinline__ float2 fft32_fwd(float2 v, const LaneTw& T, int lane){
    float2 p, d;
    p = shfl_xor_c(v, 16);
    v = (lane & 16) ? cmul(csub(p, v), T.w16) : cadd(v, p);
    p = shfl_xor_c(v, 8);
    v = (lane & 8)  ? cmul(csub(p, v), T.w8)  : cadd(v, p);
    p = shfl_xor_c(v, 4);
    v = (lane & 4)  ? cmul(csub(p, v), T.w4)  : cadd(v, p);
    p = shfl_xor_c(v, 2);
    if (lane & 2) { d = csub(p, v); v = (lane & 1) ? make_float2(d.y, -d.x) : d; }
    else            v = cadd(v, p);
    p = shfl_xor_c(v, 1);
    v = (lane & 1) ? csub(p, v) : cadd(v, p);
    return v;
}

// Exact unscaled inverse (input bit-reversed across lanes, output natural, x32).
__device__ __forceinline__ float2 fft32_inv(float2 v, const LaneTw& T, int lane){
    float2 p;
    p = shfl_xor_c(v, 1);
    v = (lane & 1) ? csub(p, v) : cadd(v, p);
    if ((lane & 2) && (lane & 1)) v = make_float2(-v.y, v.x);
    p = shfl_xor_c(v, 2);
    v = (lane & 2) ? csub(p, v) : cadd(v, p);
    if (lane & 4)  v = cmulj(v, T.w4);
    p = shfl_xor_c(v, 4);
    v = (lane & 4) ? csub(p, v) : cadd(v, p);
    if (lane & 8)  v = cmulj(v, T.w8);
    p = shfl_xor_c(v, 8);
    v = (lane & 8) ? csub(p, v) : cadd(v, p);
    if (lane & 16) v = cmulj(v, T.w16);
    p = shfl_xor_c(v, 16);
    v = (lane & 16) ? csub(p, v) : cadd(v, p);
    return v;
}

// Register FFT-8, DIF, output reg j holds X8[br3(j)].
__device__ __forceinline__ void fft8_fwd(float2 r[8]){
    const float R2 = 0.70710678118654752440f;
    float2 a, d;
    a = r[0]; r[0] = cadd(a, r[4]); r[4] = csub(a, r[4]);
    a = r[1]; d = csub(a, r[5]); r[1] = cadd(a, r[5]);
              r[5] = make_float2((d.x + d.y)*R2, (d.y - d.x)*R2);      // * (R2,-R2)
    a = r[2]; d = csub(a, r[6]); r[2] = cadd(a, r[6]);
              r[6] = make_float2(d.y, -d.x);                            // * -i
    a = r[3]; d = csub(a, r[7]); r[3] = cadd(a, r[7]);
              r[7] = make_float2((d.y - d.x)*R2, -(d.x + d.y)*R2);      // * (-R2,-R2)
    a = r[0]; r[0] = cadd(a, r[2]); r[2] = csub(a, r[2]);
    a = r[1]; d = csub(a, r[3]); r[1] = cadd(a, r[3]); r[3] = make_float2(d.y, -d.x);
    a = r[4]; r[4] = cadd(a, r[6]); r[6] = csub(a, r[6]);
    a = r[5]; d = csub(a, r[7]); r[5] = cadd(a, r[7]); r[7] = make_float2(d.y, -d.x);
    a = r[0]; r[0] = cadd(a, r[1]); r[1] = csub(a, r[1]);
    a = r[2]; r[2] = cadd(a, r[3]); r[3] = csub(a, r[3]);
    a = r[4]; r[4] = cadd(a, r[5]); r[5] = csub(a, r[5]);
    a = r[6]; r[6] = cadd(a, r[7]); r[7] = csub(a, r[7]);
}

// Exact unscaled inverse of fft8_fwd (input br3 order, output natural, x8).
__device__ __forceinline__ void fft8_inv(float2 r[8]){
    const float R2 = 0.70710678118654752440f;
    float2 a, d;
    a = r[0]; r[0] = cadd(a, r[1]); r[1] = csub(a, r[1]);
    a = r[2]; r[2] = cadd(a, r[3]); r[3] = csub(a, r[3]);
    a = r[4]; r[4] = cadd(a, r[5]); r[5] = csub(a, r[5]);
    a = r[6]; r[6] = cadd(a, r[7]); r[7] = csub(a, r[7]);
    a = r[0]; r[0] = cadd(a, r[2]); r[2] = csub(a, r[2]);
    d = make_float2(-r[3].y, r[3].x); a = r[1]; r[1] = cadd(a, d); r[3] = csub(a, d);
    a = r[4]; r[4] = cadd(a, r[6]); r[6] = csub(a, r[6]);
    d = make_float2(-r[7].y, r[7].x); a = r[5]; r[5] = cadd(a, d); r[7] = csub(a, d);
    d = r[4];                                       a = r[0]; r[0] = cadd(a, d); r[4] = csub(a, d);
    d = make_float2((r[5].x - r[5].y)*R2, (r[5].x + r[5].y)*R2);     // * (R2, R2)
                                                    a = r[1]; r[1] = cadd(a, d); r[5] = csub(a, d);
    d = make_float2(-r[6].y, r[6].x);               a = r[2]; r[2] = cadd(a, d); r[6] = csub(a, d);
    d = make_float2(-(r[7].x + r[7].y)*R2, (r[7].x - r[7].y)*R2);    // * (-R2, R2)
                                                    a = r[3]; r[3] = cadd(a, d); r[7] = csub(a, d);
}

// ---------------------------------------------------------------------------
// Forward 2048: input xt[t] = time values at n = n0 + 256t (n0 = w + 8*lane);
// output xh[v] = X[k], k = 256v + 8*lane + w.  Uses sm2[2112] transpose buffer.
// ---------------------------------------------------------------------------
__device__ __forceinline__ void fwd2048(float2 xt[8], float2 xh[8], float2* sm2,
                                        const float2 tws[8], float2 tw2,
                                        const LaneTw& T, int lane, int w)
{
    fft8_fwd(xt);                              // reg j -> digit s = br3(j)
#pragma unroll
    for (int j = 1; j < 8; j++) xt[j] = cmul(xt[j], tws[BR3(j)]);
    int c = br5(lane);
    __syncthreads();                            // protect prior readers of sm2
#pragma unroll
    for (int j = 0; j < 8; j++){
        float2 v = fft32_fwd(xt[j], T, lane);   // over lanes, per s
        v = cmul(v, tw2);                       // w_256^{w*br5(lane)}
        sm2[(w*8 + BR3(j))*33 + c] = v;         // (s, c, r=w)
    }
    __syncthreads();
    float2 m[8];
#pragma unroll
    for (int rr = 0; rr < 8; rr++) m[rr] = sm2[(rr*8 + w)*33 + lane];  // role (s=w, c=lane)
    fft8_fwd(m);                                // reg j -> v = br3(j)
#pragma unroll
    for (int v = 0; v < 8; v++) xh[v] = m[BR3(v)];
}

// Exact unscaled inverse (x2048): input q[v] spectrum, output xt[t] time.
__device__ __forceinline__ void inv2048(float2 q[8], float2 xt[8], float2* sm2,
                                        const float2 tws[8], float2 tw2,
                                        const LaneTw& T, int lane, int w)
{
    float2 r[8];
#pragma unroll
    for (int j = 0; j < 8; j++) r[j] = q[BR3(j)];
    fft8_inv(r);                                // r[rr] -> value bound for warp rr
    __syncthreads();
#pragma unroll
    for (int rr = 0; rr < 8; rr++) sm2[(rr*8 + w)*33 + lane] = r[rr];  // (s=w, c=lane, r=rr)
    __syncthreads();
    int c = br5(lane);
    float2 rs[8];
#pragma unroll
    for (int s = 0; s < 8; s++){
        float2 v = sm2[(w*8 + s)*33 + c];       // (s, c=br5(lane), r=w)
        v = cmulj(v, tw2);
        rs[s] = fft32_inv(v, T, lane);
    }
#pragma unroll
    for (int j = 0; j < 8; j++)
        xt[j] = (BR3(j) == 0) ? rs[0] : cmulj(rs[BR3(j)], tws[BR3(j)]);
    fft8_inv(xt);                               // xt[t], total x2048
}

// ---------------------------------------------------------------------------
__global__ void __launch_bounds__(NT)
precompute_kernel(const float* __restrict__ G, const float* __restrict__ H)
{
    __shared__ float2 sm2[2112];
    float* smf = (float*)sm2;
    int tid = threadIdx.x, lane = tid & 31, w = tid >> 5;
    int n0 = w + 8*lane;
    LaneTw T = make_lane_tw(lane);
    float2 tws[8];
    { float s, c; sincospif((float)n0*(1.f/1024.f), &s, &c);
      float2 b = make_float2(c, -s);
      tws[0] = make_float2(1.f, 0.f); tws[1] = b;
#pragma unroll
      for (int j = 2; j < 8; j++) tws[j] = cmul(tws[j-1], b); }
    float2 tw2;
    { float s, c; sincospif((float)(w*br5(lane))*(1.f/128.f), &s, &c); tw2 = make_float2(c, -s); }

    int wb = blockIdx.x;
    const float* src = (wb < RR) ? (G + wb*NN) : (H + (wb-RR)*NN);
    for (int idx = tid; idx < NN; idx += NT) smf[idx + (idx>>5)] = src[idx];
    __syncthreads();

    float2 xt[8];
    if (wb < RR){
#pragma unroll
        for (int t = 0; t < 8; t++){
            int n = n0 + 256*t;
            xt[t] = make_float2(smf[n + (n>>5)], 0.f);
        }
    } else {
#pragma unroll
        for (int t = 0; t < 8; t++){
            int n = n0 + 256*t;
            int j = (NN - n) & (NN - 1);
            float hv = smf[j + (j>>5)];
            float s, c; sincospif((float)j*(1.f/(float)NN), &s, &c);   // eta^j
            xt[t] = make_float2(hv*c, hv*s);
        }
    }

    float2 xh[8];
    fwd2048(xt, xh, sm2, tws, tw2, T, lane, w);

    float2* dst = (wb < RR) ? g_Ghat[wb] : g_Hhat[wb - RR];
#pragma unroll
    for (int v = 0; v < 8; v++) dst[256*v + 32*w + lane] = xh[v];
}

__global__ void __launch_bounds__(NT)
combine_kernel()
{
    int j = blockIdx.x, tid = threadIdx.x;
    const float cs = 0.5f / (float)NN;
    for (int k = tid; k < NN; k += NT){
        float2 g0 = g_Ghat[2*j][k], g1 = g_Ghat[2*j+1][k];
        float2 h0 = g_Hhat[2*j][k], h1 = g_Hhat[2*j+1][k];
        g_A[j][k]  = make_float2((g0.x + g1.y) * cs, (g0.y - g1.x) * cs);
        g_B[j][k]  = make_float2((g0.x - g1.y) * cs, (g0.y + g1.x) * cs);
        g_HH[j][k] = make_float2(h0.x - h1.y,        h0.y + h1.x);
    }
}

// ---------------------------------------------------------------------------
__global__ void __launch_bounds__(NT)
toeplitz_kernel(const float* __restrict__ x, float* __restrict__ out)
{
    __shared__ float2 sm2[2112];
    float* smf = (float*)sm2;
    int tid = threadIdx.x, lane = tid & 31, w = tid >> 5;
    int n0 = w + 8*lane;
    LaneTw T = make_lane_tw(lane);

    float2 tws[8];
    { float s, c; sincospif((float)n0*(1.f/1024.f), &s, &c);
      float2 b = make_float2(c, -s);
      tws[0] = make_float2(1.f, 0.f); tws[1] = b;
#pragma unroll
      for (int j = 2; j < 8; j++) tws[j] = cmul(tws[j-1], b); }
    float2 tw2;
    { float s, c; sincospif((float)(w*br5(lane))*(1.f/128.f), &s, &c); tw2 = make_float2(c, -s); }
    float2 etaC0;
    { float s, c; sincospif((float)n0*(1.f/(float)NN), &s, &c); etaC0 = make_float2(c, -s); }
    const float2 STEPC = make_float2(0.92387953251128674f, -0.38268343236508977f); // e^{-i pi/8}
    const float2 STEPP = make_float2(0.92387953251128674f,  0.38268343236508977f); // e^{+i pi/8}

    const float* xr = x + (size_t)blockIdx.x * NN;
    for (int idx = tid; idx < NN; idx += NT) smf[idx + (idx>>5)] = xr[idx];
    __syncthreads();

    float2 xt[8];
    { float2 cur = etaC0;                     // conj(eta)^n chain
#pragma unroll
      for (int t = 0; t < 8; t++){
          int n = n0 + 256*t;
          float v = smf[n + (n>>5)];
          xt[t] = make_float2(v*cur.x, v*cur.y);
          cur = cmul(cur, STEPC);
      } }

    float2 xh[8];
    fwd2048(xt, xh, sm2, tws, tw2, T, lane, w);   // entry sync protects float reads

    float2 y[8];
#pragma unroll
    for (int v = 0; v < 8; v++) y[v] = make_float2(0.f, 0.f);

#pragma unroll 1
    for (int jj = 0; jj < 2; jj++){
        const float2* __restrict__ HH = g_HH[jj];
        const float2* __restrict__ A  = g_A[jj];
        const float2* __restrict__ B  = g_B[jj];

        float2 q[8];
#pragma unroll
        for (int v = 0; v < 8; v++)
            q[v] = cmul(HH[256*v + 32*w + lane], xh[v]);

        float2 zt[8];
        inv2048(q, zt, sm2, tws, tw2, T, lane, w);

        { float2 cur = make_float2(etaC0.x, -etaC0.y);   // eta^{n0}
#pragma unroll
          for (int t = 0; t < 8; t++){
              zt[t] = cmul(cur, zt[t]);
              cur = cmul(cur, STEPP);
          } }

        float2 Wv[8];
        fwd2048(zt, Wv, sm2, tws, tw2, T, lane, w);

        __syncthreads();
#pragma unroll
        for (int v = 0; v < 8; v++)
            sm2[(v*8 + w)*33 + lane] = Wv[v];            // A(v, c=lane, s=w)
        __syncthreads();
#pragma unroll
        for (int v = 0; v < 8; v++){
            int k  = 256*v + 8*lane + w;
            int kn = (NN - k) & (NN - 1);
            float2 wp = sm2[((kn>>8)*8 + (kn&7))*33 + ((kn>>3)&31)];
            int fidx = 256*v + 32*w + lane;
            y[v] = cadd(y[v], cadd(cmul(A[fidx], Wv[v]), cmulj(B[fidx], wp)));
        }
    }

    float2 rt[8];
    inv2048(y, rt, sm2, tws, tw2, T, lane, w);   // entry sync protects gather reads

    __syncthreads();
#pragma unroll
    for (int t = 0; t < 8; t++){
        int n = n0 + 256*t;
        smf[n + (n>>5)] = rt[t].x * (1.f/(float)NN);
    }
    __syncthreads();

    float* orow = out + (size_t)blockIdx.x * NN;
    for (int idx = tid; idx < NN; idx += NT) orow[idx] = smf[idx + (idx>>5)];
}

// ---------------------------------------------------------------------------
extern "C" void kernel_launch(void* const* d_in, const int* in_sizes, int n_in,
                              void* d_out, int out_size)
{
    const float* x = (const float*)d_in[0];
    const float* G = (const float*)d_in[1];
    const float* H = (const float*)d_in[2];
    float* out = (float*)d_out;
    (void)in_sizes; (void)n_in; (void)out_size;

    precompute_kernel<<<2 * RR, NT>>>(G, H);
    combine_kernel<<<2, NT>>>();
    toeplitz_kernel<<<4096, NT>>>(x, out);
}